// round 14
// baseline (speedup 1.0000x reference)
#include <cuda_runtime.h>
#include <cuda_fp16.h>
#include <math.h>
#include <stdint.h>

#define NN    50000
#define EE    1600000
#define HIGHD 4096
#define LOWD  64
#define EMB   128
#define HID   128
#define OUTC  10
#define BNEPS 1e-5f
#define KCH   32
#define NCHUNK (HIGHD / KCH)        // 128
#define NBLK  ((NN + 127) / 128)    // 391
#define SC1   64.0f
#define SC1I  (1.0f / 64.0f)
#define SC2   32.0f
#define SC2I  (1.0f / 32.0f)

// ---------------- scratch ----------------
__device__ __half g_Bh[(size_t)HIGHD * EMB];
__device__ __half g_Wc2h[(size_t)2 * EMB * HID];
__device__ __half g_Zth[(size_t)NBLK * 4 * 128 * 32];
__device__ __half g_Ztl[(size_t)NBLK * 4 * 128 * 32];
__device__ __half g_XWh[(size_t)NN * HID];
__device__ float g_c1h[EMB];
__device__ float g_W1l[LOWD * EMB];
__device__ float g_c1l[EMB];
__device__ float g_crow[HID];
__device__ float g_sum_h[HIGHD], g_ssq_h[HIGHD];
__device__ float g_sum_l[LOWD],  g_ssq_l[LOWD];
__device__ float g_scale_l[LOWD], g_shift_l[LOWD];
__device__ float g_sum2[2 * EMB], g_ssq2[2 * EMB];
__device__ float g_scale2[2 * EMB], g_shift2[2 * EMB];
__device__ int   g_deg[NN];
__device__ float g_dinv[NN];
__device__ int   g_rowoff[NN + 1];
__device__ int   g_cursor[NN];
__device__ int   g_csr[EE];
__device__ int   g_is64;

// ---------------- PTX helpers ----------------
__device__ __forceinline__ uint32_t smem_u32(const void* p) {
    uint32_t a;
    asm("{ .reg .u64 t; cvta.to.shared.u64 t, %1; cvt.u32.u64 %0, t; }" : "=r"(a) : "l"(p));
    return a;
}
#define LDMX4(r, a) \
    asm volatile("ldmatrix.sync.aligned.m8n8.x4.shared.b16 {%0,%1,%2,%3}, [%4];" \
        : "=r"((r)[0]), "=r"((r)[1]), "=r"((r)[2]), "=r"((r)[3]) : "r"(a))

__device__ __forceinline__ void mma_f16(float* c, const uint32_t* a, uint32_t b0, uint32_t b1) {
    asm volatile(
        "mma.sync.aligned.m16n8k16.row.col.f32.f16.f16.f32 "
        "{%0,%1,%2,%3}, {%4,%5,%6,%7}, {%8,%9}, {%0,%1,%2,%3};"
        : "+f"(c[0]), "+f"(c[1]), "+f"(c[2]), "+f"(c[3])
        : "r"(a[0]), "r"(a[1]), "r"(a[2]), "r"(a[3]), "r"(b0), "r"(b1));
}
__device__ __forceinline__ uint32_t h2u(__half2 h) { return *reinterpret_cast<uint32_t*>(&h); }

#define CP_ASYNC16(dst, src) \
    asm volatile("cp.async.cg.shared.global [%0], [%1], 16;" :: "r"(dst), "l"(src) : "memory")
#define CP_COMMIT() asm volatile("cp.async.commit_group;" ::: "memory")
#define CP_WAIT1()  asm volatile("cp.async.wait_group 1;" ::: "memory")
#define CP_WAIT0()  asm volatile("cp.async.wait_group 0;" ::: "memory")

// ---------------- 1: zero + edge dtype detect ----------------
__global__ void zero_detect_kernel(int n, const int* __restrict__ edge_words, int e) {
    int i = blockIdx.x * blockDim.x + threadIdx.x;
    if (i < HIGHD) { g_sum_h[i] = 0.f; g_ssq_h[i] = 0.f; }
    if (i < LOWD)  { g_sum_l[i] = 0.f; g_ssq_l[i] = 0.f; }
    if (i < 2 * EMB) { g_sum2[i] = 0.f; g_ssq2[i] = 0.f; }
    if (i < n) g_deg[i] = 0;
    if (blockIdx.x == 0) {
        __shared__ int flag;
        if (threadIdx.x == 0) flag = 0;
        __syncthreads();
        int m = e < 1024 ? e : 1024;
        for (int j = threadIdx.x; j < m; j += blockDim.x)
            if (edge_words[2 * j + 1] != 0) flag = 1;
        __syncthreads();
        if (threadIdx.x == 0) g_is64 = (flag ? 0 : 1);
    }
}

// ---------------- 2: high col stats ----------------
__global__ void colstats4_kernel(const float* __restrict__ x, int n) {
    int c4 = blockIdx.x * 1024 + threadIdx.x * 4;
    float s0 = 0, s1 = 0, s2 = 0, s3 = 0, q0 = 0, q1 = 0, q2 = 0, q3 = 0;
    for (int r = blockIdx.y; r < n; r += gridDim.y) {
        float4 v = *(const float4*)&x[(size_t)r * HIGHD + c4];
        s0 += v.x; q0 += v.x * v.x;
        s1 += v.y; q1 += v.y * v.y;
        s2 += v.z; q2 += v.z * v.z;
        s3 += v.w; q3 += v.w * v.w;
    }
    atomicAdd(&g_sum_h[c4 + 0], s0); atomicAdd(&g_ssq_h[c4 + 0], q0);
    atomicAdd(&g_sum_h[c4 + 1], s1); atomicAdd(&g_ssq_h[c4 + 1], q1);
    atomicAdd(&g_sum_h[c4 + 2], s2); atomicAdd(&g_ssq_h[c4 + 2], q2);
    atomicAdd(&g_sum_h[c4 + 3], s3); atomicAdd(&g_ssq_h[c4 + 3], q3);
}

// ---------------- 3: BN1 fold high with inlined finalize ----------------
// blocks [0,2048): Wt fold (k = 2b, 2b+1 only -> recompute scale inline)
// blocks [2048,2176): bias fold (recompute shift_j inline per j)
__global__ void folds1hf_kernel(const float* __restrict__ Wh, const float* __restrict__ gh,
                                const float* __restrict__ bh, float invn) {
    __shared__ float red[256];
    int b = blockIdx.x, tx = threadIdx.x;
    if (b < 2048) {
        int i = b * 256 + tx;
        int k = i >> 7, nn = i & 127;
        float m = g_sum_h[k] * invn;
        float var = g_ssq_h[k] * invn - m * m;
        float scale = rsqrtf(var + BNEPS) * gh[k];
        float v = Wh[i] * scale * SC1;
        int c = k >> 5, kk = k & 31;
        uint32_t kb = (uint32_t)kk * 2;
        uint32_t sw = ((kb & 0x30u) ^ (((uint32_t)(nn >> 1) & 3u) << 4)) | (kb & 15u);
        g_Bh[(size_t)c * 4096 + (((uint32_t)nn * 64 + sw) >> 1)] = __float2half(v);
    } else {
        int k = b - 2048;
        float s = 0.f;
        for (int j = tx; j < HIGHD; j += 256) {
            float m = g_sum_h[j] * invn;
            float var = g_ssq_h[j] * invn - m * m;
            float scale = rsqrtf(var + BNEPS) * gh[j];
            float shift = bh[j] - m * scale;
            s += shift * Wh[(size_t)j * 128 + k];
        }
        red[tx] = s;
        __syncthreads();
        for (int off = 128; off; off >>= 1) {
            if (tx < off) red[tx] += red[tx + off];
            __syncthreads();
        }
        if (tx == 0) g_c1h[k] = bh[k] + red[0];
    }
}

// ---------------- low col stats ----------------
__global__ void colstats_low_kernel(const float* __restrict__ x, int n) {
    int t = threadIdx.x;
    int cg = t & 15, ro = t >> 4;
    int c4 = cg * 4;
    float s[4] = {0, 0, 0, 0}, q[4] = {0, 0, 0, 0};
    for (int r = blockIdx.x * 16 + ro; r < n; r += gridDim.x * 16) {
        float4 v = *(const float4*)&x[(size_t)r * LOWD + c4];
        s[0] += v.x; q[0] += v.x * v.x;
        s[1] += v.y; q[1] += v.y * v.y;
        s[2] += v.z; q[2] += v.z * v.z;
        s[3] += v.w; q[3] += v.w * v.w;
    }
    __shared__ float sh[2][64];
    if (t < 64) { sh[0][t] = 0.f; sh[1][t] = 0.f; }
    __syncthreads();
#pragma unroll
    for (int k = 0; k < 4; k++) {
        atomicAdd(&sh[0][c4 + k], s[k]);
        atomicAdd(&sh[1][c4 + k], q[k]);
    }
    __syncthreads();
    if (t < 64) { atomicAdd(&g_sum_l[t], sh[0][t]); atomicAdd(&g_ssq_l[t], sh[1][t]); }
}

// ---------------- finalize BN1 low ----------------
__global__ void finalize1l_kernel(const float* __restrict__ gl, const float* __restrict__ bl,
                                  float invn) {
    int j = threadIdx.x;
    if (j >= LOWD) return;
    float m = g_sum_l[j] * invn;
    float var = g_ssq_l[j] * invn - m * m;
    float s = rsqrtf(var + BNEPS) * gl[j];
    g_scale_l[j] = s;
    g_shift_l[j] = bl[j] - m * s;
}

// ---------------- BN1 folds low ----------------
__global__ void folds1l_kernel(const float* __restrict__ Wl, const float* __restrict__ bl) {
    __shared__ float red[256];
    int b = blockIdx.x, tx = threadIdx.x;
    if (b < 32) {
        int i = b * 256 + tx;
        g_W1l[i] = Wl[i] * g_scale_l[i >> 7];
    } else {
        int k = b - 32;
        float s = (tx < LOWD) ? g_shift_l[tx] * Wl[(size_t)tx * 128 + k] : 0.f;
        red[tx] = s;
        __syncthreads();
        for (int off = 128; off; off >>= 1) {
            if (tx < off) red[tx] += red[tx + off];
            __syncthreads();
        }
        if (tx == 0) g_c1l[k] = bl[k] + red[0];
    }
}

// ---------------- GEMM high (fp16 mma, M=128, cp.async B, double-buffered) ----------------
__global__ void __launch_bounds__(256, 2) gemm_mma_kernel(const float* __restrict__ A, int n) {
    __shared__ __align__(16) __half sA[2][128 * 32];
    __shared__ __align__(16) __half sB[2][128 * 32];
    __shared__ float ssum[128], ssqs[128];

    const int tid = threadIdx.x;
    const int wid = tid >> 5, lane = tid & 31;
    const int wm = wid & 3;
    const int wn = wid >> 2;
    const int row0 = blockIdx.x * 128;

    if (tid < 128) { ssum[tid] = 0.f; ssqs[tid] = 0.f; }

    int prow[4];
    const float* aptr[4];
    bool avalid[4];
    uint32_t sdst[4];
#pragma unroll
    for (int i = 0; i < 4; i++) {
        prow[i] = wid * 16 + i * 4 + (lane >> 3);
        avalid[i] = (row0 + prow[i]) < n;
        aptr[i] = A + (size_t)(row0 + prow[i]) * HIGHD + (lane & 7) * 4;
        sdst[i] = (uint32_t)prow[i] * 64 +
                  (((uint32_t)(lane & 7) * 8) ^ ((((uint32_t)prow[i] >> 1) & 3u) << 4));
    }
    const char* Bsrc = (const char*)g_Bh;

    const uint32_t aB0 = smem_u32(sA[0]), aB1 = smem_u32(sA[1]);
    const uint32_t bB0 = smem_u32(sB[0]), bB1 = smem_u32(sB[1]);
    const int lrA = lane & 15;
    const uint32_t lkA = ((uint32_t)(lane >> 4)) << 4;
    const uint32_t swA = (((uint32_t)(lrA >> 1) & 3u) << 4);
    const int lrB = (lane & 7) + ((lane >> 4) << 3);
    const uint32_t lkB = ((uint32_t)(lane & 8)) << 1;
    const uint32_t swB = (((uint32_t)(lrB >> 1) & 3u) << 4);

    float acc[2][8][4];
#pragma unroll
    for (int mt = 0; mt < 2; mt++)
#pragma unroll
        for (int j = 0; j < 8; j++)
#pragma unroll
            for (int q = 0; q < 4; q++) acc[mt][j][q] = 0.f;

    float4 ar[4];
#pragma unroll
    for (int j = 0; j < 2; j++)
        CP_ASYNC16(bB0 + tid * 16 + j * 4096, Bsrc + tid * 16 + j * 4096);
    CP_COMMIT();
#pragma unroll
    for (int i = 0; i < 4; i++)
        ar[i] = avalid[i] ? *(const float4*)aptr[i] : make_float4(0.f, 0.f, 0.f, 0.f);
#pragma unroll
    for (int i = 0; i < 4; i++) {
        __half2 h01 = __floats2half2_rn(ar[i].x, ar[i].y);
        __half2 h23 = __floats2half2_rn(ar[i].z, ar[i].w);
        *(uint2*)((char*)sA[0] + sdst[i]) = make_uint2(h2u(h01), h2u(h23));
    }

    for (int c = 0; c < NCHUNK; c++) {
        __syncthreads();
        if (c + 1 < NCHUNK) {
#pragma unroll
            for (int i = 0; i < 4; i++)
                ar[i] = avalid[i] ? *(const float4*)(aptr[i] + (c + 1) * KCH)
                                  : make_float4(0.f, 0.f, 0.f, 0.f);
            uint32_t db = ((c + 1) & 1) ? bB1 : bB0;
            const char* src = Bsrc + (size_t)(c + 1) * 8192;
#pragma unroll
            for (int j = 0; j < 2; j++)
                CP_ASYNC16(db + tid * 16 + j * 4096, src + tid * 16 + j * 4096);
            CP_COMMIT();
            CP_WAIT1();
        } else {
            CP_WAIT0();
        }
        __syncthreads();
        const uint32_t aB = (c & 1) ? aB1 : aB0;
        const uint32_t bB = (c & 1) ? bB1 : bB0;
#pragma unroll
        for (int ks = 0; ks < 2; ks++) {
            uint32_t af[2][4];
#pragma unroll
            for (int mt = 0; mt < 2; mt++) {
                uint32_t off = (uint32_t)(wm * 32 + mt * 16 + lrA) * 64 +
                               (((uint32_t)(ks * 32) + lkA) ^ swA);
                LDMX4(af[mt], aB + off);
            }
#pragma unroll
            for (int g4 = 0; g4 < 4; g4++) {
                uint32_t boff = (uint32_t)(wn * 64 + g4 * 16 + lrB) * 64 +
                                (((uint32_t)(ks * 32) + lkB) ^ swB);
                uint32_t bf[4];
                LDMX4(bf, bB + boff);
#pragma unroll
                for (int mt = 0; mt < 2; mt++) {
                    mma_f16(acc[mt][g4 * 2 + 0], af[mt], bf[0], bf[1]);
                    mma_f16(acc[mt][g4 * 2 + 1], af[mt], bf[2], bf[3]);
                }
            }
        }
        if (c + 1 < NCHUNK) {
            __half* dA = sA[(c + 1) & 1];
#pragma unroll
            for (int i = 0; i < 4; i++) {
                __half2 h01 = __floats2half2_rn(ar[i].x, ar[i].y);
                __half2 h23 = __floats2half2_rn(ar[i].z, ar[i].w);
                *(uint2*)((char*)dA + sdst[i]) = make_uint2(h2u(h01), h2u(h23));
            }
        }
    }

    const int g = lane >> 2, t4 = lane & 3;
    __half* zt = g_Zth + (size_t)blockIdx.x * 16384;
#pragma unroll
    for (int j = 0; j < 8; j++) {
        int col = wn * 64 + j * 8 + t4 * 2;
        int chunk = col >> 5;
        uint32_t kb = (uint32_t)(col & 31) * 2;
        float c1a = g_c1h[col], c1b = g_c1h[col + 1];
        float sa = 0.f, sb = 0.f, qa = 0.f, qb = 0.f;
#pragma unroll
        for (int mt = 0; mt < 2; mt++) {
#pragma unroll
            for (int h = 0; h < 2; h++) {
                int rloc = wm * 32 + mt * 16 + g + h * 8;
                float x0 = fmaxf(acc[mt][j][h * 2 + 0] * SC1I + c1a, 0.f);
                float x1 = fmaxf(acc[mt][j][h * 2 + 1] * SC1I + c1b, 0.f);
                uint32_t bo = (uint32_t)chunk * 8192 + (uint32_t)rloc * 64 +
                              (kb ^ ((((uint32_t)rloc >> 1) & 3u) << 4));
                *(__half2*)((char*)zt + bo) = __floats2half2_rn(x0, x1);
                if (row0 + rloc < n) { sa += x0; sb += x1; qa += x0 * x0; qb += x1 * x1; }
            }
        }
        atomicAdd(&ssum[col], sa); atomicAdd(&ssum[col + 1], sb);
        atomicAdd(&ssqs[col], qa); atomicAdd(&ssqs[col + 1], qb);
    }
    __syncthreads();
    if (tid < 128) {
        atomicAdd(&g_sum2[tid], ssum[tid]);
        atomicAdd(&g_ssq2[tid], ssqs[tid]);
    }
}

// ---------------- GEMM low (f32 SIMT) ----------------
__global__ __launch_bounds__(256) void gemm_relu_stats_kernel(const float* __restrict__ A, int n) {
    __shared__ float As[16][128];
    __shared__ float Bs[16][128];
    const int tx = threadIdx.x;
    const int trow = tx >> 4, tcol = tx & 15;
    const int row0 = blockIdx.x * 128;

    float acc[8][8];
#pragma unroll
    for (int i = 0; i < 8; i++)
#pragma unroll
        for (int j = 0; j < 8; j++) acc[i][j] = 0.f;

    for (int k0 = 0; k0 < LOWD; k0 += 16) {
#pragma unroll
        for (int i = 0; i < 2; i++) {
            int f = tx + i * 256;
            int r = f >> 2;
            int kc = (f & 3) << 2;
            int gr = row0 + r;
            float4 v = make_float4(0.f, 0.f, 0.f, 0.f);
            if (gr < n) v = *(const float4*)&A[(size_t)gr * LOWD + k0 + kc];
            As[kc + 0][r] = v.x; As[kc + 1][r] = v.y; As[kc + 2][r] = v.z; As[kc + 3][r] = v.w;
        }
#pragma unroll
        for (int i = 0; i < 2; i++) {
            int f = tx + i * 256;
            int r = f >> 5;
            int cc = (f & 31) << 2;
            *(float4*)&Bs[r][cc] = *(const float4*)&g_W1l[(size_t)(k0 + r) * 128 + cc];
        }
        __syncthreads();
#pragma unroll
        for (int k = 0; k < 16; k++) {
            float a[8], b[8];
            *(float4*)&a[0] = *(const float4*)&As[k][trow * 8];
            *(float4*)&a[4] = *(const float4*)&As[k][trow * 8 + 4];
            *(float4*)&b[0] = *(const float4*)&Bs[k][tcol * 8];
            *(float4*)&b[4] = *(const float4*)&Bs[k][tcol * 8 + 4];
#pragma unroll
            for (int i = 0; i < 8; i++)
#pragma unroll
                for (int j = 0; j < 8; j++) acc[i][j] += a[i] * b[j];
        }
        __syncthreads();
    }

    float cs[8], cq[8], c1v[8];
#pragma unroll
    for (int j = 0; j < 8; j++) { cs[j] = 0.f; cq[j] = 0.f; c1v[j] = g_c1l[tcol * 8 + j]; }

    __half* zt = g_Ztl + (size_t)blockIdx.x * 16384;
    const int chunk = tcol >> 2;
    const uint32_t unit = (uint32_t)(tcol & 3) * 16;
#pragma unroll
    for (int i = 0; i < 8; i++) {
        int rloc = trow * 8 + i;
        int gr = row0 + rloc;
        float z[8];
#pragma unroll
        for (int j = 0; j < 8; j++) {
            float v = acc[i][j] + c1v[j];
            z[j] = v > 0.f ? v : 0.f;
        }
        if (gr < n) {
#pragma unroll
            for (int j = 0; j < 8; j++) { cs[j] += z[j]; cq[j] += z[j] * z[j]; }
        }
        __half2 p0 = __floats2half2_rn(z[0], z[1]);
        __half2 p1 = __floats2half2_rn(z[2], z[3]);
        __half2 p2 = __floats2half2_rn(z[4], z[5]);
        __half2 p3 = __floats2half2_rn(z[6], z[7]);
        uint32_t bo = (uint32_t)chunk * 8192 + (uint32_t)rloc * 64 +
                      (unit ^ ((((uint32_t)rloc >> 1) & 3u) << 4));
        *(uint4*)((char*)zt + bo) = make_uint4(h2u(p0), h2u(p1), h2u(p2), h2u(p3));
    }
    __syncthreads();
#pragma unroll
    for (int j = 0; j < 8; j++) As[trow][tcol * 8 + j] = cs[j];
    __syncthreads();
    if (tx < 128) {
        float s = 0.f;
#pragma unroll
        for (int r = 0; r < 16; r++) s += As[r][tx];
        atomicAdd(&g_sum2[EMB + tx], s);
    }
    __syncthreads();
#pragma unroll
    for (int j = 0; j < 8; j++) As[trow][tcol * 8 + j] = cq[j];
    __syncthreads();
    if (tx < 128) {
        float s = 0.f;
#pragma unroll
        for (int r = 0; r < 16; r++) s += As[r][tx];
        atomicAdd(&g_ssq2[EMB + tx], s);
    }
}

// ---------------- finalize BN2 ----------------
__global__ void finalize2_kernel(const float* __restrict__ gh, const float* __restrict__ bh,
                                 const float* __restrict__ gl, const float* __restrict__ bl,
                                 float invn) {
    int i = threadIdx.x;
    const float* gg = (i < EMB) ? gh : gl;
    const float* bb = (i < EMB) ? bh : bl;
    int j = i & (EMB - 1);
    float m = g_sum2[i] * invn;
    float var = g_ssq2[i] * invn - m * m;
    float s = rsqrtf(var + BNEPS) * gg[j];
    g_scale2[i] = s;
    g_shift2[i] = bb[j] - m * s;
}

// ---------------- fold BN2 into conv1 ----------------
__global__ void folds2_kernel(const float* __restrict__ W) {
    __shared__ float red[256];
    int b = blockIdx.x, tx = threadIdx.x;
    if (b < 128) {
        int i = b * 256 + tx;
        int k = i >> 7, nn = i & 127;
        float v = W[i] * g_scale2[k] * SC2;
        int c = k >> 5, kk = k & 31;
        uint32_t kb = (uint32_t)kk * 2;
        uint32_t sw = ((kb & 0x30u) ^ (((uint32_t)(nn >> 1) & 3u) << 4)) | (kb & 15u);
        g_Wc2h[(size_t)c * 4096 + (((uint32_t)nn * 64 + sw) >> 1)] = __float2half(v);
    } else {
        int k = b - 128;
        float s = g_shift2[tx] * W[(size_t)tx * 128 + k];
        red[tx] = s;
        __syncthreads();
        for (int off = 128; off; off >>= 1) {
            if (tx < off) red[tx] += red[tx + off];
            __syncthreads();
        }
        if (tx == 0) g_crow[k] = red[0];
    }
}

// ---------------- GEMM 2 (fp16 mma, double-buffered) ----------------
__global__ void __launch_bounds__(256, 2) gemm2_kernel(int n) {
    __shared__ __align__(16) __half sA[2][128 * 32];
    __shared__ __align__(16) __half sB[2][128 * 32];

    const int tid = threadIdx.x;
    const int wid = tid >> 5, lane = tid & 31;
    const int wm = wid & 3, wn = wid >> 2;
    const int row0 = blockIdx.x * 128;

    const uint4* At = (const uint4*)(g_Zth + (size_t)blockIdx.x * 16384);
    const uint4* Al = (const uint4*)(g_Ztl + (size_t)blockIdx.x * 16384);
    const uint4* Bt = (const uint4*)g_Wc2h;

    const uint32_t aB0 = smem_u32(sA[0]), aB1 = smem_u32(sA[1]);
    const uint32_t bB0 = smem_u32(sB[0]), bB1 = smem_u32(sB[1]);
    const int lrA = lane & 15;
    const uint32_t lkA = ((uint32_t)(lane >> 4)) << 4;
    const uint32_t swA = (((uint32_t)(lrA >> 1) & 3u) << 4);
    const int lrB = (lane & 7) + ((lane >> 4) << 3);
    const uint32_t lkB = ((uint32_t)(lane & 8)) << 1;
    const uint32_t swB = (((uint32_t)(lrB >> 1) & 3u) << 4);

    float acc[2][8][4];
#pragma unroll
    for (int mt = 0; mt < 2; mt++)
#pragma unroll
        for (int j = 0; j < 8; j++)
#pragma unroll
            for (int q = 0; q < 4; q++) acc[mt][j][q] = 0.f;

    uint4 a4[2], b4[2];
    a4[0] = At[tid]; a4[1] = At[tid + 256];
    b4[0] = Bt[tid]; b4[1] = Bt[tid + 256];
    ((uint4*)sA[0])[tid] = a4[0]; ((uint4*)sA[0])[tid + 256] = a4[1];
    ((uint4*)sB[0])[tid] = b4[0]; ((uint4*)sB[0])[tid + 256] = b4[1];

    for (int c = 0; c < 8; c++) {
        __syncthreads();
        if (c + 1 < 8) {
            const uint4* src = (c + 1 < 4) ? (At + (size_t)(c + 1) * 512) : (Al + (size_t)(c - 3) * 512);
            a4[0] = src[tid]; a4[1] = src[tid + 256];
            b4[0] = Bt[(size_t)(c + 1) * 512 + tid]; b4[1] = Bt[(size_t)(c + 1) * 512 + tid + 256];
        }
        const uint32_t aB = (c & 1) ? aB1 : aB0;
        const uint32_t bB = (c & 1) ? bB1 : bB0;
#pragma unroll
        for (int ks = 0; ks < 2; ks++) {
            uint32_t af[2][4];
#pragma unroll
            for (int mt = 0; mt < 2; mt++) {
                uint32_t off = (uint32_t)(wm * 32 + mt * 16 + lrA) * 64 +
                               (((uint32_t)(ks * 32) + lkA) ^ swA);
                LDMX4(af[mt], aB + off);
            }
#pragma unroll
            for (int g4 = 0; g4 < 4; g4++) {
                uint32_t boff = (uint32_t)(wn * 64 + g4 * 16 + lrB) * 64 +
                                (((uint32_t)(ks * 32) + lkB) ^ swB);
                uint32_t bf[4];
                LDMX4(bf, bB + boff);
#pragma unroll
                for (int mt = 0; mt < 2; mt++) {
                    mma_f16(acc[mt][g4 * 2 + 0], af[mt], bf[0], bf[1]);
                    mma_f16(acc[mt][g4 * 2 + 1], af[mt], bf[2], bf[3]);
                }
            }
        }
        if (c + 1 < 8) {
            __half* dA = sA[(c + 1) & 1];
            __half* dB = sB[(c + 1) & 1];
            ((uint4*)dA)[tid] = a4[0]; ((uint4*)dA)[tid + 256] = a4[1];
            ((uint4*)dB)[tid] = b4[0]; ((uint4*)dB)[tid + 256] = b4[1];
        }
    }

    const int g = lane >> 2, t4 = lane & 3;
#pragma unroll
    for (int j = 0; j < 8; j++) {
        int col = wn * 64 + j * 8 + t4 * 2;
        float ca = g_crow[col], cb = g_crow[col + 1];
#pragma unroll
        for (int mt = 0; mt < 2; mt++)
#pragma unroll
            for (int h = 0; h < 2; h++) {
                int r = row0 + wm * 32 + mt * 16 + g + h * 8;
                if (r < n) {
                    float x0 = acc[mt][j][h * 2 + 0] * SC2I + ca;
                    float x1 = acc[mt][j][h * 2 + 1] * SC2I + cb;
                    *(__half2*)&g_XWh[(size_t)r * 128 + col] = __floats2half2_rn(x0, x1);
                }
            }
    }
}

// ---------------- graph machinery ----------------
__device__ __forceinline__ int edge_at(const void* edge, int e, int which_row, int i) {
    if (g_is64) {
        const long long* p = (const long long*)edge;
        return (int)p[(size_t)which_row * e + i];
    } else {
        const int* p = (const int*)edge;
        return p[(size_t)which_row * e + i];
    }
}

__global__ void deg_kernel(const void* __restrict__ edge, int e) {
    for (int i = blockIdx.x * blockDim.x + threadIdx.x; i < e; i += gridDim.x * blockDim.x) {
        int d = edge_at(edge, e, 1, i);
        atomicAdd(&g_deg[d], 1);
    }
}

__global__ void scan_kernel(int n) {
    __shared__ int wsum[32];
    __shared__ int s_carry;
    int tx = threadIdx.x, lane = tx & 31, wid = tx >> 5;
    if (tx == 0) { s_carry = 0; g_rowoff[0] = 0; }
    __syncthreads();
    for (int base = 0; base < n; base += 1024) {
        int i = base + tx;
        int v = (i < n) ? g_deg[i] : 0;
        if (i < n) g_dinv[i] = rsqrtf((float)(v + 1));
        int inc = v;
#pragma unroll
        for (int off = 1; off < 32; off <<= 1) {
            int t = __shfl_up_sync(0xffffffffu, inc, off);
            if (lane >= off) inc += t;
        }
        if (lane == 31) wsum[wid] = inc;
        __syncthreads();
        if (wid == 0) {
            int w = wsum[lane];
            int wi = w;
#pragma unroll
            for (int off = 1; off < 32; off <<= 1) {
                int t = __shfl_up_sync(0xffffffffu, wi, off);
                if (lane >= off) wi += t;
            }
            wsum[lane] = wi - w;
        }
        __syncthreads();
        int incl = inc + wsum[wid] + s_carry;
        if (i < n) {
            g_rowoff[i + 1] = incl;
            g_cursor[i] = incl - v;
        }
        __syncthreads();
        if (tx == 1023) s_carry = incl;
        __syncthreads();
    }
}

__global__ void fill_kernel(const void* __restrict__ edge, int e) {
    for (int i = blockIdx.x * blockDim.x + threadIdx.x; i < e; i += gridDim.x * blockDim.x) {
        int d = edge_at(edge, e, 1, i);
        int s = edge_at(edge, e, 0, i);
        int p = atomicAdd(&g_cursor[d], 1);
        g_csr[p] = s;
    }
}

// ---------------- gather + tanh + classifier + log_softmax ----------------
__global__ void gather_kernel(const float* __restrict__ convb, const float* __restrict__ clsW,
                              const float* __restrict__ clsb, float* __restrict__ out, int n) {
    int gw = (blockIdx.x * blockDim.x + threadIdx.x) >> 5;
    int lane = threadIdx.x & 31;
    if (gw >= n) return;
    const float di = g_dinv[gw];
    const uint2* xw2 = (const uint2*)g_XWh;

    uint2 u = xw2[(size_t)gw * 32 + lane];
    float2 f0 = __half22float2(*(__half2*)&u.x);
    float2 f1 = __half22float2(*(__half2*)&u.y);
    float ax = f0.x * di, ay = f0.y * di, az = f1.x * di, aw = f1.y * di;

    int beg = g_rowoff[gw], end = g_rowoff[gw + 1];
    int j = beg;
    for (; j + 3 < end; j += 4) {
        int s0 = g_csr[j], s1 = g_csr[j + 1], s2 = g_csr[j + 2], s3 = g_csr[j + 3];
        float w0 = g_dinv[s0], w1 = g_dinv[s1], w2 = g_dinv[s2], w3 = g_dinv[s3];
        uint2 v0 = xw2[(size_t)s0 * 32 + lane];
        uint2 v1 = xw2[(size_t)s1 * 32 + lane];
        uint2 v2 = xw2[(size_t)s2 * 32 + lane];
        uint2 v3 = xw2[(size_t)s3 * 32 + lane];
        float2 a0 = __half22float2(*(__half2*)&v0.x), b0 = __half22float2(*(__half2*)&v0.y);
        float2 a1 = __half22float2(*(__half2*)&v1.x), b1 = __half22float2(*(__half2*)&v1.y);
        float2 a2 = __half22float2(*(__half2*)&v2.x), b2 = __half22float2(*(__half2*)&v2.y);
        float2 a3 = __half22float2(*(__half2*)&v3.x), b3 = __half22float2(*(__half2*)&v3.y);
        ax += a0.x * w0 + a1.x * w1 + a2.x * w2 + a3.x * w3;
        ay += a0.y * w0 + a1.y * w1 + a2.y * w2 + a3.y * w3;
        az += b0.x * w0 + b1.x * w1 + b2.x * w2 + b3.x * w3;
        aw += b0.y * w0 + b1.y * w1 + b2.y * w2 + b3.y * w3;
    }
    for (; j < end; j++) {
        int s = g_csr[j];
        float w = g_dinv[s];
        uint2 v = xw2[(size_t)s * 32 + lane];
        float2 v0 = __half22float2(*(__half2*)&v.x);
        float2 v1 = __half22float2(*(__half2*)&v.y);
        ax += v0.x * w; ay += v0.y * w; az += v1.x * w; aw += v1.y * w;
    }
    float4 cb = ((const float4*)convb)[lane];
    float h0 = tanhf(ax * di + cb.x);
    float h1 = tanhf(ay * di + cb.y);
    float h2 = tanhf(az * di + cb.z);
    float h3 = tanhf(aw * di + cb.w);

    int c0 = lane * 4;
    float lo[OUTC];
#pragma unroll
    for (int o = 0; o < OUTC; o++) {
        lo[o] = h0 * clsW[(size_t)c0 * OUTC + o]
              + h1 * clsW[(size_t)(c0 + 1) * OUTC + o]
              + h2 * clsW[(size_t)(c0 + 2) * OUTC + o]
              + h3 * clsW[(size_t)(c0 + 3) * OUTC + o];
    }
#pragma unroll
    for (int off = 16; off; off >>= 1)
#pragma unroll
        for (int o = 0; o < OUTC; o++)
            lo[o] += __shfl_xor_sync(0xffffffffu, lo[o], off);

    if (lane == 0) {
        float m = -1e30f;
#pragma unroll
        for (int o = 0; o < OUTC; o++) { lo[o] += clsb[o]; m = fmaxf(m, lo[o]); }
        float s = 0.f;
#pragma unroll
        for (int o = 0; o < OUTC; o++) s += expf(lo[o] - m);
        float lse = m + logf(s);
#pragma unroll
        for (int o = 0; o < OUTC; o++) out[(size_t)gw * OUTC + o] = lo[o] - lse;
    }
}

// ---------------- launch ----------------
extern "C" void kernel_launch(void* const* d_in, const int* in_sizes, int n_in,
                              void* d_out, int out_size) {
    const float* low_x      = (const float*)d_in[1];
    const float* cov_x      = (const float*)d_in[2];
    const void*  edge       = d_in[3];
    const float* bn_low_g   = (const float*)d_in[4];
    const float* bn_low_b   = (const float*)d_in[5];
    const float* bn_high_g  = (const float*)d_in[6];
    const float* bn_high_b  = (const float*)d_in[7];
    const float* lin_low_W  = (const float*)d_in[8];
    const float* lin_low_b  = (const float*)d_in[9];
    const float* mlp_low_g  = (const float*)d_in[10];
    const float* mlp_low_b  = (const float*)d_in[11];
    const float* lin_high_W = (const float*)d_in[12];
    const float* lin_high_b = (const float*)d_in[13];
    const float* mlp_high_g = (const float*)d_in[14];
    const float* mlp_high_b = (const float*)d_in[15];
    const float* conv1_W    = (const float*)d_in[16];
    const float* conv1_b    = (const float*)d_in[17];
    const float* cls_W      = (const float*)d_in[18];
    const float* cls_b      = (const float*)d_in[19];

    int n = in_sizes[1] / LOWD;
    int e = in_sizes[3] / 2;
    float invn = 1.f / (float)n;
    int nblk = (n + 127) / 128;

    static cudaStream_t s_graph = 0, s_low = 0;
    static cudaEvent_t  s_evFork = 0, s_evLow = 0, s_evGraph = 0;
    if (!s_graph) {
        cudaStreamCreateWithFlags(&s_graph, cudaStreamNonBlocking);
        cudaStreamCreateWithFlags(&s_low, cudaStreamNonBlocking);
        cudaEventCreateWithFlags(&s_evFork, cudaEventDisableTiming);
        cudaEventCreateWithFlags(&s_evLow, cudaEventDisableTiming);
        cudaEventCreateWithFlags(&s_evGraph, cudaEventDisableTiming);
    }

    // submissions 1-4 on main (our 4th submission gets profiled by ncu -s 5)
    zero_detect_kernel<<<(n + 255) / 256, 256>>>(n, (const int*)edge, e);      // 1
    colstats4_kernel<<<dim3(HIGHD / 1024, 256), 256>>>(cov_x, n);              // 2
    folds1hf_kernel<<<2176, 256>>>(lin_high_W, bn_high_g, bn_high_b, invn);    // 3
    gemm_mma_kernel<<<nblk, 256>>>(cov_x, n);                                  // 4 (profiled)

    // fork event recorded after zero (deps for both side streams)
    cudaEventRecord(s_evFork, 0);   // records after gemm in main, but side streams
                                    // only need zero_detect; still correct (later is safe)
    cudaStreamWaitEvent(s_graph, s_evFork, 0);
    cudaStreamWaitEvent(s_low, s_evFork, 0);

    // low path (side stream 2)
    colstats_low_kernel<<<128, 256, 0, s_low>>>(low_x, n);
    finalize1l_kernel<<<1, 64, 0, s_low>>>(bn_low_g, bn_low_b, invn);
    folds1l_kernel<<<160, 256, 0, s_low>>>(lin_low_W, lin_low_b);
    gemm_relu_stats_kernel<<<nblk, 256, 0, s_low>>>(low_x, n);
    cudaEventRecord(s_evLow, s_low);

    // graph build (side stream 1)
    deg_kernel<<<2048, 256, 0, s_graph>>>(edge, e);
    scan_kernel<<<1, 1024, 0, s_graph>>>(n);
    fill_kernel<<<2048, 256, 0, s_graph>>>(edge, e);
    cudaEventRecord(s_evGraph, s_graph);

    // join low stats -> BN2 fold -> conv GEMM
    cudaStreamWaitEvent(0, s_evLow, 0);
    finalize2_kernel<<<1, 256>>>(mlp_high_g, mlp_high_b, mlp_low_g, mlp_low_b, invn);
    folds2_kernel<<<256, 256>>>(conv1_W);
    gemm2_kernel<<<nblk, 256>>>(n);

    // join graph -> aggregate + epilogue
    cudaStreamWaitEvent(0, s_evGraph, 0);
    gather_kernel<<<(n * 32 + 255) / 256, 256>>>(conv1_b, cls_W, cls_b, (float*)d_out, n);
}

// round 15
// speedup vs baseline: 1.1215x; 1.1215x over previous
#include <cuda_runtime.h>
#include <cuda_fp16.h>
#include <math.h>
#include <stdint.h>

#define NN    50000
#define EE    1600000
#define HIGHD 4096
#define LOWD  64
#define EMB   128
#define HID   128
#define OUTC  10
#define BNEPS 1e-5f
#define KCH   32
#define NCHUNK (HIGHD / KCH)        // 128
#define NBLK  ((NN + 127) / 128)    // 391
#define SC1   64.0f
#define SC1I  (1.0f / 64.0f)
#define SC2   32.0f
#define SC2I  (1.0f / 32.0f)

// ---------------- scratch ----------------
__device__ __half g_A16[(size_t)NBLK * 128 * HIGHD];   // fp16 copy of cov_x (+ zero tail rows)
__device__ __half g_Bh[(size_t)HIGHD * EMB];
__device__ __half g_Wc2h[(size_t)2 * EMB * HID];
__device__ __half g_Zth[(size_t)NBLK * 4 * 128 * 32];
__device__ __half g_Ztl[(size_t)NBLK * 4 * 128 * 32];
__device__ __half g_XWh[(size_t)NN * HID];
__device__ float g_c1h[EMB];
__device__ float g_W1l[LOWD * EMB];
__device__ float g_c1l[EMB];
__device__ float g_crow[HID];
__device__ float g_sum_h[HIGHD], g_ssq_h[HIGHD];
__device__ float g_sum_l[LOWD],  g_ssq_l[LOWD];
__device__ float g_scale_l[LOWD], g_shift_l[LOWD];
__device__ float g_sum2[2 * EMB], g_ssq2[2 * EMB];
__device__ float g_scale2[2 * EMB], g_shift2[2 * EMB];
__device__ int   g_deg[NN];
__device__ float g_dinv[NN];
__device__ int   g_rowoff[NN + 1];
__device__ int   g_cursor[NN];
__device__ int   g_csr[EE];
__device__ int   g_is64;

// ---------------- PTX helpers ----------------
__device__ __forceinline__ uint32_t smem_u32(const void* p) {
    uint32_t a;
    asm("{ .reg .u64 t; cvta.to.shared.u64 t, %1; cvt.u32.u64 %0, t; }" : "=r"(a) : "l"(p));
    return a;
}
#define LDMX4(r, a) \
    asm volatile("ldmatrix.sync.aligned.m8n8.x4.shared.b16 {%0,%1,%2,%3}, [%4];" \
        : "=r"((r)[0]), "=r"((r)[1]), "=r"((r)[2]), "=r"((r)[3]) : "r"(a))

__device__ __forceinline__ void mma_f16(float* c, const uint32_t* a, uint32_t b0, uint32_t b1) {
    asm volatile(
        "mma.sync.aligned.m16n8k16.row.col.f32.f16.f16.f32 "
        "{%0,%1,%2,%3}, {%4,%5,%6,%7}, {%8,%9}, {%0,%1,%2,%3};"
        : "+f"(c[0]), "+f"(c[1]), "+f"(c[2]), "+f"(c[3])
        : "r"(a[0]), "r"(a[1]), "r"(a[2]), "r"(a[3]), "r"(b0), "r"(b1));
}
__device__ __forceinline__ uint32_t h2u(__half2 h) { return *reinterpret_cast<uint32_t*>(&h); }

#define CP_ASYNC16(dst, src) \
    asm volatile("cp.async.cg.shared.global [%0], [%1], 16;" :: "r"(dst), "l"(src) : "memory")
#define CP_COMMIT() asm volatile("cp.async.commit_group;" ::: "memory")
#define CP_WAITG1() asm volatile("cp.async.wait_group 1;" ::: "memory")

// ---------------- 1: zero + edge dtype detect + A16 tail zero ----------------
__global__ void zero_detect_kernel(int n, int totrows, const int* __restrict__ edge_words, int e) {
    int i = blockIdx.x * blockDim.x + threadIdx.x;
    int gsz = gridDim.x * blockDim.x;
    if (i < HIGHD) { g_sum_h[i] = 0.f; g_ssq_h[i] = 0.f; }
    if (i < LOWD)  { g_sum_l[i] = 0.f; g_ssq_l[i] = 0.f; }
    if (i < 2 * EMB) { g_sum2[i] = 0.f; g_ssq2[i] = 0.f; }
    if (i < n) g_deg[i] = 0;
    // zero A16 tail rows [n, totrows)
    size_t tail = (size_t)(totrows - n) * 2048;  // uint32 count (4096 halves/row)
    uint32_t* tz = (uint32_t*)(g_A16 + (size_t)n * HIGHD);
    for (size_t idx = i; idx < tail; idx += gsz) tz[idx] = 0;
    if (blockIdx.x == 0) {
        __shared__ int flag;
        if (threadIdx.x == 0) flag = 0;
        __syncthreads();
        int m = e < 1024 ? e : 1024;
        for (int j = threadIdx.x; j < m; j += blockDim.x)
            if (edge_words[2 * j + 1] != 0) flag = 1;
        __syncthreads();
        if (threadIdx.x == 0) g_is64 = (flag ? 0 : 1);
    }
}

// ---------------- 2: high col stats + fp16 conversion ----------------
__global__ void colstats4_kernel(const float* __restrict__ x, int n) {
    int c4 = blockIdx.x * 1024 + threadIdx.x * 4;
    float s0 = 0, s1 = 0, s2 = 0, s3 = 0, q0 = 0, q1 = 0, q2 = 0, q3 = 0;
    for (int r = blockIdx.y; r < n; r += gridDim.y) {
        float4 v = *(const float4*)&x[(size_t)r * HIGHD + c4];
        s0 += v.x; q0 += v.x * v.x;
        s1 += v.y; q1 += v.y * v.y;
        s2 += v.z; q2 += v.z * v.z;
        s3 += v.w; q3 += v.w * v.w;
        __half2 h01 = __floats2half2_rn(v.x, v.y);
        __half2 h23 = __floats2half2_rn(v.z, v.w);
        *(uint2*)&g_A16[(size_t)r * HIGHD + c4] = make_uint2(h2u(h01), h2u(h23));
    }
    atomicAdd(&g_sum_h[c4 + 0], s0); atomicAdd(&g_ssq_h[c4 + 0], q0);
    atomicAdd(&g_sum_h[c4 + 1], s1); atomicAdd(&g_ssq_h[c4 + 1], q1);
    atomicAdd(&g_sum_h[c4 + 2], s2); atomicAdd(&g_ssq_h[c4 + 2], q2);
    atomicAdd(&g_sum_h[c4 + 3], s3); atomicAdd(&g_ssq_h[c4 + 3], q3);
}

// ---------------- 3: BN1 fold high with inlined finalize ----------------
__global__ void folds1hf_kernel(const float* __restrict__ Wh, const float* __restrict__ gh,
                                const float* __restrict__ bh, float invn) {
    __shared__ float red[256];
    int b = blockIdx.x, tx = threadIdx.x;
    if (b < 2048) {
        int i = b * 256 + tx;
        int k = i >> 7, nn = i & 127;
        float m = g_sum_h[k] * invn;
        float var = g_ssq_h[k] * invn - m * m;
        float scale = rsqrtf(var + BNEPS) * gh[k];
        float v = Wh[i] * scale * SC1;
        int c = k >> 5, kk = k & 31;
        uint32_t kb = (uint32_t)kk * 2;
        uint32_t sw = ((kb & 0x30u) ^ (((uint32_t)(nn >> 1) & 3u) << 4)) | (kb & 15u);
        g_Bh[(size_t)c * 4096 + (((uint32_t)nn * 64 + sw) >> 1)] = __float2half(v);
    } else {
        int k = b - 2048;
        float s = 0.f;
        for (int j = tx; j < HIGHD; j += 256) {
            float m = g_sum_h[j] * invn;
            float var = g_ssq_h[j] * invn - m * m;
            float scale = rsqrtf(var + BNEPS) * gh[j];
            float shift = bh[j] - m * scale;
            s += shift * Wh[(size_t)j * 128 + k];
        }
        red[tx] = s;
        __syncthreads();
        for (int off = 128; off; off >>= 1) {
            if (tx < off) red[tx] += red[tx + off];
            __syncthreads();
        }
        if (tx == 0) g_c1h[k] = bh[k] + red[0];
    }
}

// ---------------- low col stats ----------------
__global__ void colstats_low_kernel(const float* __restrict__ x, int n) {
    int t = threadIdx.x;
    int cg = t & 15, ro = t >> 4;
    int c4 = cg * 4;
    float s[4] = {0, 0, 0, 0}, q[4] = {0, 0, 0, 0};
    for (int r = blockIdx.x * 16 + ro; r < n; r += gridDim.x * 16) {
        float4 v = *(const float4*)&x[(size_t)r * LOWD + c4];
        s[0] += v.x; q[0] += v.x * v.x;
        s[1] += v.y; q[1] += v.y * v.y;
        s[2] += v.z; q[2] += v.z * v.z;
        s[3] += v.w; q[3] += v.w * v.w;
    }
    __shared__ float sh[2][64];
    if (t < 64) { sh[0][t] = 0.f; sh[1][t] = 0.f; }
    __syncthreads();
#pragma unroll
    for (int k = 0; k < 4; k++) {
        atomicAdd(&sh[0][c4 + k], s[k]);
        atomicAdd(&sh[1][c4 + k], q[k]);
    }
    __syncthreads();
    if (t < 64) { atomicAdd(&g_sum_l[t], sh[0][t]); atomicAdd(&g_ssq_l[t], sh[1][t]); }
}

// ---------------- finalize BN1 low ----------------
__global__ void finalize1l_kernel(const float* __restrict__ gl, const float* __restrict__ bl,
                                  float invn) {
    int j = threadIdx.x;
    if (j >= LOWD) return;
    float m = g_sum_l[j] * invn;
    float var = g_ssq_l[j] * invn - m * m;
    float s = rsqrtf(var + BNEPS) * gl[j];
    g_scale_l[j] = s;
    g_shift_l[j] = bl[j] - m * s;
}

// ---------------- BN1 folds low ----------------
__global__ void folds1l_kernel(const float* __restrict__ Wl, const float* __restrict__ bl) {
    __shared__ float red[256];
    int b = blockIdx.x, tx = threadIdx.x;
    if (b < 32) {
        int i = b * 256 + tx;
        g_W1l[i] = Wl[i] * g_scale_l[i >> 7];
    } else {
        int k = b - 32;
        float s = (tx < LOWD) ? g_shift_l[tx] * Wl[(size_t)tx * 128 + k] : 0.f;
        red[tx] = s;
        __syncthreads();
        for (int off = 128; off; off >>= 1) {
            if (tx < off) red[tx] += red[tx + off];
            __syncthreads();
        }
        if (tx == 0) g_c1l[k] = bl[k] + red[0];
    }
}

// ---------------- GEMM high: fp16 A16 + B via 3-stage cp.async, 1 barrier/chunk ----------------
__global__ void __launch_bounds__(256, 2) gemm_mma_kernel(int n) {
    __shared__ __align__(16) __half sA[3][128 * 32];
    __shared__ __align__(16) __half sB[3][128 * 32];
    __shared__ float ssum[128], ssqs[128];

    const int tid = threadIdx.x;
    const int wid = tid >> 5, lane = tid & 31;
    const int wm = wid & 3;
    const int wn = wid >> 2;
    const int row0 = blockIdx.x * 128;

    if (tid < 128) { ssum[tid] = 0.f; ssqs[tid] = 0.f; }

    // producer: thread t -> row t>>1, 32B half-row segment (t&1)
    const uint32_t aRow = (uint32_t)(tid >> 1);
    const char* Asrc = (const char*)g_A16 + (size_t)(row0 + aRow) * (HIGHD * 2) + (uint32_t)(tid & 1) * 32;
    const uint32_t aSw = ((aRow >> 1) & 3u) << 4;
    const uint32_t aKb = (uint32_t)(tid & 1) * 32;
    const uint32_t adst0 = aRow * 64 + ((aKb + 0) ^ aSw);
    const uint32_t adst1 = aRow * 64 + ((aKb + 16) ^ aSw);
    const char* Bsrc = (const char*)g_Bh;

    uint32_t aS[3], bS[3];
#pragma unroll
    for (int s = 0; s < 3; s++) { aS[s] = smem_u32(sA[s]); bS[s] = smem_u32(sB[s]); }

    const int lrA = lane & 15;
    const uint32_t lkA = ((uint32_t)(lane >> 4)) << 4;
    const uint32_t swA = (((uint32_t)(lrA >> 1) & 3u) << 4);
    const int lrB = (lane & 7) + ((lane >> 4) << 3);
    const uint32_t lkB = ((uint32_t)(lane & 8)) << 1;
    const uint32_t swB = (((uint32_t)(lrB >> 1) & 3u) << 4);

    float acc[2][8][4];
#pragma unroll
    for (int mt = 0; mt < 2; mt++)
#pragma unroll
        for (int j = 0; j < 8; j++)
#pragma unroll
            for (int q = 0; q < 4; q++) acc[mt][j][q] = 0.f;

    // prologue: stages 0, 1
#pragma unroll
    for (int s = 0; s < 2; s++) {
        CP_ASYNC16(aS[s] + adst0, Asrc + (size_t)s * 64);
        CP_ASYNC16(aS[s] + adst1, Asrc + (size_t)s * 64 + 16);
        CP_ASYNC16(bS[s] + tid * 16,        Bsrc + (size_t)s * 8192 + tid * 16);
        CP_ASYNC16(bS[s] + tid * 16 + 4096, Bsrc + (size_t)s * 8192 + tid * 16 + 4096);
        CP_COMMIT();
    }

    int buf = 0;
    for (int c = 0; c < NCHUNK; c++) {
        CP_WAITG1();         // this thread's stage c complete (<=1 pending)
        __syncthreads();     // all threads' stage c visible; compute c-1 fully done
        if (c + 2 < NCHUNK) {
            int s = (buf + 2 >= 3) ? buf - 1 : buf + 2;
            CP_ASYNC16(aS[s] + adst0, Asrc + (size_t)(c + 2) * 64);
            CP_ASYNC16(aS[s] + adst1, Asrc + (size_t)(c + 2) * 64 + 16);
            CP_ASYNC16(bS[s] + tid * 16,        Bsrc + (size_t)(c + 2) * 8192 + tid * 16);
            CP_ASYNC16(bS[s] + tid * 16 + 4096, Bsrc + (size_t)(c + 2) * 8192 + tid * 16 + 4096);
        }
        CP_COMMIT();         // always commit (empty group keeps wait_group accounting)

        const uint32_t aB = aS[buf];
        const uint32_t bB = bS[buf];
#pragma unroll
        for (int ks = 0; ks < 2; ks++) {
            uint32_t af[2][4];
#pragma unroll
            for (int mt = 0; mt < 2; mt++) {
                uint32_t off = (uint32_t)(wm * 32 + mt * 16 + lrA) * 64 +
                               (((uint32_t)(ks * 32) + lkA) ^ swA);
                LDMX4(af[mt], aB + off);
            }
#pragma unroll
            for (int g4 = 0; g4 < 4; g4++) {
                uint32_t boff = (uint32_t)(wn * 64 + g4 * 16 + lrB) * 64 +
                                (((uint32_t)(ks * 32) + lkB) ^ swB);
                uint32_t bf[4];
                LDMX4(bf, bB + boff);
#pragma unroll
                for (int mt = 0; mt < 2; mt++) {
                    mma_f16(acc[mt][g4 * 2 + 0], af[mt], bf[0], bf[1]);
                    mma_f16(acc[mt][g4 * 2 + 1], af[mt], bf[2], bf[3]);
                }
            }
        }
        buf = (buf + 1 == 3) ? 0 : buf + 1;
    }

    // epilogue: bias + relu + tiled fp16 Z + BN2 stats
    const int g = lane >> 2, t4 = lane & 3;
    __half* zt = g_Zth + (size_t)blockIdx.x * 16384;
#pragma unroll
    for (int j = 0; j < 8; j++) {
        int col = wn * 64 + j * 8 + t4 * 2;
        int chunk = col >> 5;
        uint32_t kb = (uint32_t)(col & 31) * 2;
        float c1a = g_c1h[col], c1b = g_c1h[col + 1];
        float sa = 0.f, sb = 0.f, qa = 0.f, qb = 0.f;
#pragma unroll
        for (int mt = 0; mt < 2; mt++) {
#pragma unroll
            for (int h = 0; h < 2; h++) {
                int rloc = wm * 32 + mt * 16 + g + h * 8;
                float x0 = fmaxf(acc[mt][j][h * 2 + 0] * SC1I + c1a, 0.f);
                float x1 = fmaxf(acc[mt][j][h * 2 + 1] * SC1I + c1b, 0.f);
                uint32_t bo = (uint32_t)chunk * 8192 + (uint32_t)rloc * 64 +
                              (kb ^ ((((uint32_t)rloc >> 1) & 3u) << 4));
                *(__half2*)((char*)zt + bo) = __floats2half2_rn(x0, x1);
                if (row0 + rloc < n) { sa += x0; sb += x1; qa += x0 * x0; qb += x1 * x1; }
            }
        }
        atomicAdd(&ssum[col], sa); atomicAdd(&ssum[col + 1], sb);
        atomicAdd(&ssqs[col], qa); atomicAdd(&ssqs[col + 1], qb);
    }
    __syncthreads();
    if (tid < 128) {
        atomicAdd(&g_sum2[tid], ssum[tid]);
        atomicAdd(&g_ssq2[tid], ssqs[tid]);
    }
}

// ---------------- GEMM low (f32 SIMT) ----------------
__global__ __launch_bounds__(256) void gemm_relu_stats_kernel(const float* __restrict__ A, int n) {
    __shared__ float As[16][128];
    __shared__ float Bs[16][128];
    const int tx = threadIdx.x;
    const int trow = tx >> 4, tcol = tx & 15;
    const int row0 = blockIdx.x * 128;

    float acc[8][8];
#pragma unroll
    for (int i = 0; i < 8; i++)
#pragma unroll
        for (int j = 0; j < 8; j++) acc[i][j] = 0.f;

    for (int k0 = 0; k0 < LOWD; k0 += 16) {
#pragma unroll
        for (int i = 0; i < 2; i++) {
            int f = tx + i * 256;
            int r = f >> 2;
            int kc = (f & 3) << 2;
            int gr = row0 + r;
            float4 v = make_float4(0.f, 0.f, 0.f, 0.f);
            if (gr < n) v = *(const float4*)&A[(size_t)gr * LOWD + k0 + kc];
            As[kc + 0][r] = v.x; As[kc + 1][r] = v.y; As[kc + 2][r] = v.z; As[kc + 3][r] = v.w;
        }
#pragma unroll
        for (int i = 0; i < 2; i++) {
            int f = tx + i * 256;
            int r = f >> 5;
            int cc = (f & 31) << 2;
            *(float4*)&Bs[r][cc] = *(const float4*)&g_W1l[(size_t)(k0 + r) * 128 + cc];
        }
        __syncthreads();
#pragma unroll
        for (int k = 0; k < 16; k++) {
            float a[8], b[8];
            *(float4*)&a[0] = *(const float4*)&As[k][trow * 8];
            *(float4*)&a[4] = *(const float4*)&As[k][trow * 8 + 4];
            *(float4*)&b[0] = *(const float4*)&Bs[k][tcol * 8];
            *(float4*)&b[4] = *(const float4*)&Bs[k][tcol * 8 + 4];
#pragma unroll
            for (int i = 0; i < 8; i++)
#pragma unroll
                for (int j = 0; j < 8; j++) acc[i][j] += a[i] * b[j];
        }
        __syncthreads();
    }

    float cs[8], cq[8], c1v[8];
#pragma unroll
    for (int j = 0; j < 8; j++) { cs[j] = 0.f; cq[j] = 0.f; c1v[j] = g_c1l[tcol * 8 + j]; }

    __half* zt = g_Ztl + (size_t)blockIdx.x * 16384;
    const int chunk = tcol >> 2;
    const uint32_t unit = (uint32_t)(tcol & 3) * 16;
#pragma unroll
    for (int i = 0; i < 8; i++) {
        int rloc = trow * 8 + i;
        int gr = row0 + rloc;
        float z[8];
#pragma unroll
        for (int j = 0; j < 8; j++) {
            float v = acc[i][j] + c1v[j];
            z[j] = v > 0.f ? v : 0.f;
        }
        if (gr < n) {
#pragma unroll
            for (int j = 0; j < 8; j++) { cs[j] += z[j]; cq[j] += z[j] * z[j]; }
        }
        __half2 p0 = __floats2half2_rn(z[0], z[1]);
        __half2 p1 = __floats2half2_rn(z[2], z[3]);
        __half2 p2 = __floats2half2_rn(z[4], z[5]);
        __half2 p3 = __floats2half2_rn(z[6], z[7]);
        uint32_t bo = (uint32_t)chunk * 8192 + (uint32_t)rloc * 64 +
                      (unit ^ ((((uint32_t)rloc >> 1) & 3u) << 4));
        *(uint4*)((char*)zt + bo) = make_uint4(h2u(p0), h2u(p1), h2u(p2), h2u(p3));
    }
    __syncthreads();
#pragma unroll
    for (int j = 0; j < 8; j++) As[trow][tcol * 8 + j] = cs[j];
    __syncthreads();
    if (tx < 128) {
        float s = 0.f;
#pragma unroll
        for (int r = 0; r < 16; r++) s += As[r][tx];
        atomicAdd(&g_sum2[EMB + tx], s);
    }
    __syncthreads();
#pragma unroll
    for (int j = 0; j < 8; j++) As[trow][tcol * 8 + j] = cq[j];
    __syncthreads();
    if (tx < 128) {
        float s = 0.f;
#pragma unroll
        for (int r = 0; r < 16; r++) s += As[r][tx];
        atomicAdd(&g_ssq2[EMB + tx], s);
    }
}

// ---------------- finalize BN2 ----------------
__global__ void finalize2_kernel(const float* __restrict__ gh, const float* __restrict__ bh,
                                 const float* __restrict__ gl, const float* __restrict__ bl,
                                 float invn) {
    int i = threadIdx.x;
    const float* gg = (i < EMB) ? gh : gl;
    const float* bb = (i < EMB) ? bh : bl;
    int j = i & (EMB - 1);
    float m = g_sum2[i] * invn;
    float var = g_ssq2[i] * invn - m * m;
    float s = rsqrtf(var + BNEPS) * gg[j];
    g_scale2[i] = s;
    g_shift2[i] = bb[j] - m * s;
}

// ---------------- fold BN2 into conv1 ----------------
__global__ void folds2_kernel(const float* __restrict__ W) {
    __shared__ float red[256];
    int b = blockIdx.x, tx = threadIdx.x;
    if (b < 128) {
        int i = b * 256 + tx;
        int k = i >> 7, nn = i & 127;
        float v = W[i] * g_scale2[k] * SC2;
        int c = k >> 5, kk = k & 31;
        uint32_t kb = (uint32_t)kk * 2;
        uint32_t sw = ((kb & 0x30u) ^ (((uint32_t)(nn >> 1) & 3u) << 4)) | (kb & 15u);
        g_Wc2h[(size_t)c * 4096 + (((uint32_t)nn * 64 + sw) >> 1)] = __float2half(v);
    } else {
        int k = b - 128;
        float s = g_shift2[tx] * W[(size_t)tx * 128 + k];
        red[tx] = s;
        __syncthreads();
        for (int off = 128; off; off >>= 1) {
            if (tx < off) red[tx] += red[tx + off];
            __syncthreads();
        }
        if (tx == 0) g_crow[k] = red[0];
    }
}

// ---------------- GEMM 2 (fp16 mma, double-buffered) ----------------
__global__ void __launch_bounds__(256, 2) gemm2_kernel(int n) {
    __shared__ __align__(16) __half sA[2][128 * 32];
    __shared__ __align__(16) __half sB[2][128 * 32];

    const int tid = threadIdx.x;
    const int wid = tid >> 5, lane = tid & 31;
    const int wm = wid & 3, wn = wid >> 2;
    const int row0 = blockIdx.x * 128;

    const uint4* At = (const uint4*)(g_Zth + (size_t)blockIdx.x * 16384);
    const uint4* Al = (const uint4*)(g_Ztl + (size_t)blockIdx.x * 16384);
    const uint4* Bt = (const uint4*)g_Wc2h;

    const uint32_t aB0 = smem_u32(sA[0]), aB1 = smem_u32(sA[1]);
    const uint32_t bB0 = smem_u32(sB[0]), bB1 = smem_u32(sB[1]);
    const int lrA = lane & 15;
    const uint32_t lkA = ((uint32_t)(lane >> 4)) << 4;
    const uint32_t swA = (((uint32_t)(lrA >> 1) & 3u) << 4);
    const int lrB = (lane & 7) + ((lane >> 4) << 3);
    const uint32_t lkB = ((uint32_t)(lane & 8)) << 1;
    const uint32_t swB = (((uint32_t)(lrB >> 1) & 3u) << 4);

    float acc[2][8][4];
#pragma unroll
    for (int mt = 0; mt < 2; mt++)
#pragma unroll
        for (int j = 0; j < 8; j++)
#pragma unroll
            for (int q = 0; q < 4; q++) acc[mt][j][q] = 0.f;

    uint4 a4[2], b4[2];
    a4[0] = At[tid]; a4[1] = At[tid + 256];
    b4[0] = Bt[tid]; b4[1] = Bt[tid + 256];
    ((uint4*)sA[0])[tid] = a4[0]; ((uint4*)sA[0])[tid + 256] = a4[1];
    ((uint4*)sB[0])[tid] = b4[0]; ((uint4*)sB[0])[tid + 256] = b4[1];

    for (int c = 0; c < 8; c++) {
        __syncthreads();
        if (c + 1 < 8) {
            const uint4* src = (c + 1 < 4) ? (At + (size_t)(c + 1) * 512) : (Al + (size_t)(c - 3) * 512);
            a4[0] = src[tid]; a4[1] = src[tid + 256];
            b4[0] = Bt[(size_t)(c + 1) * 512 + tid]; b4[1] = Bt[(size_t)(c + 1) * 512 + tid + 256];
        }
        const uint32_t aB = (c & 1) ? aB1 : aB0;
        const uint32_t bB = (c & 1) ? bB1 : bB0;
#pragma unroll
        for (int ks = 0; ks < 2; ks++) {
            uint32_t af[2][4];
#pragma unroll
            for (int mt = 0; mt < 2; mt++) {
                uint32_t off = (uint32_t)(wm * 32 + mt * 16 + lrA) * 64 +
                               (((uint32_t)(ks * 32) + lkA) ^ swA);
                LDMX4(af[mt], aB + off);
            }
#pragma unroll
            for (int g4 = 0; g4 < 4; g4++) {
                uint32_t boff = (uint32_t)(wn * 64 + g4 * 16 + lrB) * 64 +
                                (((uint32_t)(ks * 32) + lkB) ^ swB);
                uint32_t bf[4];
                LDMX4(bf, bB + boff);
#pragma unroll
                for (int mt = 0; mt < 2; mt++) {
                    mma_f16(acc[mt][g4 * 2 + 0], af[mt], bf[0], bf[1]);
                    mma_f16(acc[mt][g4 * 2 + 1], af[mt], bf[2], bf[3]);
                }
            }
        }
        if (c + 1 < 8) {
            __half* dA = sA[(c + 1) & 1];
            __half* dB = sB[(c + 1) & 1];
            ((uint4*)dA)[tid] = a4[0]; ((uint4*)dA)[tid + 256] = a4[1];
            ((uint4*)dB)[tid] = b4[0]; ((uint4*)dB)[tid + 256] = b4[1];
        }
    }

    const int g = lane >> 2, t4 = lane & 3;
#pragma unroll
    for (int j = 0; j < 8; j++) {
        int col = wn * 64 + j * 8 + t4 * 2;
        float ca = g_crow[col], cb = g_crow[col + 1];
#pragma unroll
        for (int mt = 0; mt < 2; mt++)
#pragma unroll
            for (int h = 0; h < 2; h++) {
                int r = row0 + wm * 32 + mt * 16 + g + h * 8;
                if (r < n) {
                    float x0 = acc[mt][j][h * 2 + 0] * SC2I + ca;
                    float x1 = acc[mt][j][h * 2 + 1] * SC2I + cb;
                    *(__half2*)&g_XWh[(size_t)r * 128 + col] = __floats2half2_rn(x0, x1);
                }
            }
    }
}

// ---------------- graph machinery ----------------
__device__ __forceinline__ int edge_at(const void* edge, int e, int which_row, int i) {
    if (g_is64) {
        const long long* p = (const long long*)edge;
        return (int)p[(size_t)which_row * e + i];
    } else {
        const int* p = (const int*)edge;
        return p[(size_t)which_row * e + i];
    }
}

__global__ void deg_kernel(const void* __restrict__ edge, int e) {
    for (int i = blockIdx.x * blockDim.x + threadIdx.x; i < e; i += gridDim.x * blockDim.x) {
        int d = edge_at(edge, e, 1, i);
        atomicAdd(&g_deg[d], 1);
    }
}

__global__ void scan_kernel(int n) {
    __shared__ int wsum[32];
    __shared__ int s_carry;
    int tx = threadIdx.x, lane = tx & 31, wid = tx >> 5;
    if (tx == 0) { s_carry = 0; g_rowoff[0] = 0; }
    __syncthreads();
    for (int base = 0; base < n; base += 1024) {
        int i = base + tx;
        int v = (i < n) ? g_deg[i] : 0;
        if (i < n) g_dinv[i] = rsqrtf((float)(v + 1));
        int inc = v;
#pragma unroll
        for (int off = 1; off < 32; off <<= 1) {
            int t = __shfl_up_sync(0xffffffffu, inc, off);
            if (lane >= off) inc += t;
        }
        if (lane == 31) wsum[wid] = inc;
        __syncthreads();
        if (wid == 0) {
            int w = wsum[lane];
            int wi = w;
#pragma unroll
            for (int off = 1; off < 32; off <<= 1) {
                int t = __shfl_up_sync(0xffffffffu, wi, off);
                if (lane >= off) wi += t;
            }
            wsum[lane] = wi - w;
        }
        __syncthreads();
        int incl = inc + wsum[wid] + s_carry;
        if (i < n) {
            g_rowoff[i + 1] = incl;
            g_cursor[i] = incl - v;
        }
        __syncthreads();
        if (tx == 1023) s_carry = incl;
        __syncthreads();
    }
}

__global__ void fill_kernel(const void* __restrict__ edge, int e) {
    for (int i = blockIdx.x * blockDim.x + threadIdx.x; i < e; i += gridDim.x * blockDim.x) {
        int d = edge_at(edge, e, 1, i);
        int s = edge_at(edge, e, 0, i);
        int p = atomicAdd(&g_cursor[d], 1);
        g_csr[p] = s;
    }
}

// ---------------- gather + tanh + classifier + log_softmax ----------------
__global__ void gather_kernel(const float* __restrict__ convb, const float* __restrict__ clsW,
                              const float* __restrict__ clsb, float* __restrict__ out, int n) {
    int gw = (blockIdx.x * blockDim.x + threadIdx.x) >> 5;
    int lane = threadIdx.x & 31;
    if (gw >= n) return;
    const float di = g_dinv[gw];
    const uint2* xw2 = (const uint2*)g_XWh;

    uint2 u = xw2[(size_t)gw * 32 + lane];
    float2 f0 = __half22float2(*(__half2*)&u.x);
    float2 f1 = __half22float2(*(__half2*)&u.y);
    float ax = f0.x * di, ay = f0.y * di, az = f1.x * di, aw = f1.y * di;

    int beg = g_rowoff[gw], end = g_rowoff[gw + 1];
    int j = beg;
    for (; j + 3 < end; j += 4) {
        int s0 = g_csr[j], s1 = g_csr[j + 1], s2 = g_csr[j + 2], s3 = g_csr[j + 3];
        float w0 = g_dinv[s0], w1 = g_dinv[s1], w2 = g_dinv[s2], w3 = g_dinv[s3];
        uint2 v0 = xw2[(size_t)s0 * 32 + lane];
        uint2 v1 = xw2[(size_t)s1 * 32 + lane];
        uint2 v2 = xw2[(size_t)s2 * 32 + lane];
        uint2 v3 = xw2[(size_t)s3 * 32 + lane];
        float2 a0 = __half22float2(*(__half2*)&v0.x), b0 = __half22float2(*(__half2*)&v0.y);
        float2 a1 = __half22float2(*(__half2*)&v1.x), b1 = __half22float2(*(__half2*)&v1.y);
        float2 a2 = __half22float2(*(__half2*)&v2.x), b2 = __half22float2(*(__half2*)&v2.y);
        float2 a3 = __half22float2(*(__half2*)&v3.x), b3 = __half22float2(*(__half2*)&v3.y);
        ax += a0.x * w0 + a1.x * w1 + a2.x * w2 + a3.x * w3;
        ay += a0.y * w0 + a1.y * w1 + a2.y * w2 + a3.y * w3;
        az += b0.x * w0 + b1.x * w1 + b2.x * w2 + b3.x * w3;
        aw += b0.y * w0 + b1.y * w1 + b2.y * w2 + b3.y * w3;
    }
    for (; j < end; j++) {
        int s = g_csr[j];
        float w = g_dinv[s];
        uint2 v = xw2[(size_t)s * 32 + lane];
        float2 v0 = __half22float2(*(__half2*)&v.x);
        float2 v1 = __half22float2(*(__half2*)&v.y);
        ax += v0.x * w; ay += v0.y * w; az += v1.x * w; aw += v1.y * w;
    }
    float4 cb = ((const float4*)convb)[lane];
    float h0 = tanhf(ax * di + cb.x);
    float h1 = tanhf(ay * di + cb.y);
    float h2 = tanhf(az * di + cb.z);
    float h3 = tanhf(aw * di + cb.w);

    int c0 = lane * 4;
    float lo[OUTC];
#pragma unroll
    for (int o = 0; o < OUTC; o++) {
        lo[o] = h0 * clsW[(size_t)c0 * OUTC + o]
              + h1 * clsW[(size_t)(c0 + 1) * OUTC + o]
              + h2 * clsW[(size_t)(c0 + 2) * OUTC + o]
              + h3 * clsW[(size_t)(c0 + 3) * OUTC + o];
    }
#pragma unroll
    for (int off = 16; off; off >>= 1)
#pragma unroll
        for (int o = 0; o < OUTC; o++)
            lo[o] += __shfl_xor_sync(0xffffffffu, lo[o], off);

    if (lane == 0) {
        float m = -1e30f;
#pragma unroll
        for (int o = 0; o < OUTC; o++) { lo[o] += clsb[o]; m = fmaxf(m, lo[o]); }
        float s = 0.f;
#pragma unroll
        for (int o = 0; o < OUTC; o++) s += expf(lo[o] - m);
        float lse = m + logf(s);
#pragma unroll
        for (int o = 0; o < OUTC; o++) out[(size_t)gw * OUTC + o] = lo[o] - lse;
    }
}

// ---------------- launch ----------------
extern "C" void kernel_launch(void* const* d_in, const int* in_sizes, int n_in,
                              void* d_out, int out_size) {
    const float* low_x      = (const float*)d_in[1];
    const float* cov_x      = (const float*)d_in[2];
    const void*  edge       = d_in[3];
    const float* bn_low_g   = (const float*)d_in[4];
    const float* bn_low_b   = (const float*)d_in[5];
    const float* bn_high_g  = (const float*)d_in[6];
    const float* bn_high_b  = (const float*)d_in[7];
    const float* lin_low_W  = (const float*)d_in[8];
    const float* lin_low_b  = (const float*)d_in[9];
    const float* mlp_low_g  = (const float*)d_in[10];
    const float* mlp_low_b  = (const float*)d_in[11];
    const float* lin_high_W = (const float*)d_in[12];
    const float* lin_high_b = (const float*)d_in[13];
    const float* mlp_high_g = (const float*)d_in[14];
    const float* mlp_high_b = (const float*)d_in[15];
    const float* conv1_W    = (const float*)d_in[16];
    const float* conv1_b    = (const float*)d_in[17];
    const float* cls_W      = (const float*)d_in[18];
    const float* cls_b      = (const float*)d_in[19];

    int n = in_sizes[1] / LOWD;
    int e = in_sizes[3] / 2;
    float invn = 1.f / (float)n;
    int nblk = (n + 127) / 128;

    static cudaStream_t s_graph = 0, s_low = 0;
    static cudaEvent_t  s_evFork = 0, s_evLow = 0, s_evGraph = 0;
    if (!s_graph) {
        cudaStreamCreateWithFlags(&s_graph, cudaStreamNonBlocking);
        cudaStreamCreateWithFlags(&s_low, cudaStreamNonBlocking);
        cudaEventCreateWithFlags(&s_evFork, cudaEventDisableTiming);
        cudaEventCreateWithFlags(&s_evLow, cudaEventDisableTiming);
        cudaEventCreateWithFlags(&s_evGraph, cudaEventDisableTiming);
    }

    // init; fork recorded IMMEDIATELY after so side streams overlap the feature path
    zero_detect_kernel<<<(n + 255) / 256, 256>>>(n, nblk * 128, (const int*)edge, e);
    cudaEventRecord(s_evFork, 0);
    cudaStreamWaitEvent(s_graph, s_evFork, 0);
    cudaStreamWaitEvent(s_low, s_evFork, 0);

    // graph build (side stream 1)
    deg_kernel<<<2048, 256, 0, s_graph>>>(edge, e);
    scan_kernel<<<1, 1024, 0, s_graph>>>(n);
    fill_kernel<<<2048, 256, 0, s_graph>>>(edge, e);
    cudaEventRecord(s_evGraph, s_graph);

    // low path (side stream 2)
    colstats_low_kernel<<<128, 256, 0, s_low>>>(low_x, n);
    finalize1l_kernel<<<1, 64, 0, s_low>>>(bn_low_g, bn_low_b, invn);
    folds1l_kernel<<<160, 256, 0, s_low>>>(lin_low_W, lin_low_b);
    gemm_relu_stats_kernel<<<nblk, 256, 0, s_low>>>(low_x, n);
    cudaEventRecord(s_evLow, s_low);

    // main: high feature path
    colstats4_kernel<<<dim3(HIGHD / 1024, 256), 256>>>(cov_x, n);
    folds1hf_kernel<<<2176, 256>>>(lin_high_W, bn_high_g, bn_high_b, invn);
    gemm_mma_kernel<<<nblk, 256>>>(n);

    // join low stats -> BN2 fold -> conv GEMM
    cudaStreamWaitEvent(0, s_evLow, 0);
    finalize2_kernel<<<1, 256>>>(mlp_high_g, mlp_high_b, mlp_low_g, mlp_low_b, invn);
    folds2_kernel<<<256, 256>>>(conv1_W);
    gemm2_kernel<<<nblk, 256>>>(n);

    // join graph -> aggregate + epilogue
    cudaStreamWaitEvent(0, s_evGraph, 0);
    gather_kernel<<<(n * 32 + 255) / 256, 256>>>(conv1_b, cls_W, cls_b, (float*)d_out, n);
}